// round 13
// baseline (speedup 1.0000x reference)
#include <cuda_runtime.h>

typedef unsigned long long u64;

#define NQ     10
#define NGEN   4
#define QDEPTH 6
#define WPB    4   // warps per block

// Parity-of-adjacent-pairs mask for 5-bit k: bit k = popc(k & (k>>1)) & 1.
#define MK_CONST 0x4748B848u
constexpr unsigned mk_check() {
    unsigned m = 0;
    for (int k = 0; k < 32; ++k) {
        int p = 0;
        for (int bb = 0; bb < 4; ++bb) p ^= ((k >> bb) & 1) & ((k >> (bb + 1)) & 1);
        m |= (unsigned)p << k;
    }
    return m;
}
static_assert(mk_check() == MK_CONST, "MK mask mismatch");

// ---- packed f32x2 helpers (SASS FFMA2 — PTX-only on sm_103a) ----
__device__ __forceinline__ u64 fma2(u64 a, u64 b, u64 c) {
    u64 d; asm("fma.rn.f32x2 %0, %1, %2, %3;" : "=l"(d) : "l"(a), "l"(b), "l"(c)); return d;
}
__device__ __forceinline__ u64 pack2(float lo, float hi) {
    u64 d; asm("mov.b64 %0, {%1, %2};" : "=l"(d) : "f"(lo), "f"(hi)); return d;
}
__device__ __forceinline__ void unpack2(u64 v, float& lo, float& hi) {
    asm("mov.b64 {%0, %1}, %2;" : "=f"(lo), "=f"(hi) : "l"(v));
}
__device__ __forceinline__ u64 swap32(u64 v) {
    return (v << 32) | (v >> 32);
}

// ---- RY via shear/lifting: 3 FMA per pair. Rotation phi: nt=-tan(phi/2), sn=sin(phi).
template<int M>
__device__ __forceinline__ void ry2_shear(u64 (&v)[32], u64 nt, u64 sn) {
    #pragma unroll
    for (int k = 0; k < 32; ++k) if (!(k & M)) {
        const int j = k | M;
        u64 a0 = v[k], a1 = v[j];
        a0 = fma2(nt, a1, a0);
        a1 = fma2(sn, a0, a1);
        a0 = fma2(nt, a1, a0);
        v[k] = a0; v[j] = a1;
    }
}

// ---- RX via shear on crossed components: (a0r,a1i) rotate by -phi, (a0i,a1r) by +phi.
// Packed: u=a0, p=swap(a1); NT=(t,-t), SN=(-s,s) with t=tan(phi/2), s=sin(phi).
// u'=u+NT*p; p'=p+SN*u'; u''=u'+NT*p'; a0=u'', a1=swap(p').
template<int M>
__device__ __forceinline__ void rx2_shear(u64 (&v)[32], u64 rnt, u64 rsn) {
    #pragma unroll
    for (int k = 0; k < 32; ++k) if (!(k & M)) {
        const int j = k | M;
        u64 u = v[k], p = swap32(v[j]);
        u = fma2(rnt, p, u);
        p = fma2(rsn, u, p);
        u = fma2(rnt, p, u);
        v[k] = u; v[j] = swap32(p);
    }
}

template<int M>
__device__ __forceinline__ float exv(const u64 (&v)[32]) {
    u64 acc0 = 0ull, acc1 = 0ull, acc2 = 0ull, acc3 = 0ull;
    #pragma unroll
    for (int k = 0; k < 32; k += 4) {
        acc0 = fma2(v[k + 0], v[(k + 0) ^ M], acc0);
        acc1 = fma2(v[k + 1], v[(k + 1) ^ M], acc1);
        acc2 = fma2(v[k + 2], v[(k + 2) ^ M], acc2);
        acc3 = fma2(v[k + 3], v[(k + 3) ^ M], acc3);
    }
    float l0, h0, l1, h1, l2, h2, l3, h3;
    unpack2(acc0, l0, h0); unpack2(acc1, l1, h1);
    unpack2(acc2, l2, h2); unpack2(acc3, l3, h3);
    return (l0 + h0) + (l1 + h1) + ((l2 + h2) + (l3 + h3));
}

// CZ-chain diagonal: predicated sign flip (compile-time bit per reg)
__device__ __forceinline__ void cz_apply(u64 (&v)[32], unsigned sgn) {
    #pragma unroll
    for (int k = 0; k < 32; ++k)
        if (sgn & (1u << k)) v[k] ^= 0x8000000080000000ull;
}

// 32x32 warp transpose through padded smem (stride-34 u64 rows).
__device__ __forceinline__ void transpose(u64 (&v)[32], u64* t, unsigned lane) {
    __syncwarp();
    #pragma unroll
    for (int r = 0; r < 32; r += 2)
        *reinterpret_cast<ulonglong2*>(t + lane * 34u + r) = make_ulonglong2(v[r], v[r + 1]);
    __syncwarp();
    #pragma unroll
    for (int k = 0; k < 32; ++k)
        v[k] = t[k * 34u + lane];
}

// 5 shear-RY gates; consts are pre-packed u64 in smem (one LDS.64 broadcast each)
__device__ __forceinline__ void half5(u64 (&v)[32],
                                      const u64* __restrict__ nt2,
                                      const u64* __restrict__ sn2,
                                      int base) {
    ry2_shear<16>(v, nt2[base + 0], sn2[base + 0]);
    ry2_shear<8>(v,  nt2[base + 1], sn2[base + 1]);
    ry2_shear<4>(v,  nt2[base + 2], sn2[base + 2]);
    ry2_shear<2>(v,  nt2[base + 3], sn2[base + 3]);
    ry2_shear<1>(v,  nt2[base + 4], sn2[base + 4]);
}

// one init wire: shear-RY then shear-RX, pre-packed consts
template<int M>
__device__ __forceinline__ void init_wire(u64 (&v)[32],
                                          const u64* __restrict__ iy_nt,
                                          const u64* __restrict__ iy_sn,
                                          const u64* __restrict__ ir_nt,
                                          const u64* __restrict__ ir_sn,
                                          int q) {
    ry2_shear<M>(v, iy_nt[q], iy_sn[q]);
    rx2_shear<M>(v, ir_nt[q], ir_sn[q]);
}

// ===== Fused kernel: one warp per (b, g) =====
// Layout A: i = lane*32 + k (register wires 5..9)
// Layout B: i = k*32 + lane (register wires 0..4)
__global__ void __launch_bounds__(32 * WPB, 4)
qgen_fused(const float* __restrict__ noise,
           const float* __restrict__ qp,
           float* __restrict__ out, int batch)
{
    __shared__ u64 tile[WPB][32 * 34];
    __shared__ u64 tnt2[WPB][64], tsn2[WPB][64];                // tail RY shear (packed)
    __shared__ u64 iynt[WPB][16], iysn[WPB][16];                // init RY shear (packed)
    __shared__ u64 irnt[WPB][16], irsn[WPB][16];                // init RX shear (packed)

    const unsigned lane = threadIdx.x & 31u;
    const unsigned w    = threadIdx.x >> 5;
    const unsigned wid  = blockIdx.x * WPB + w;
    const unsigned b    = wid >> 2;          // 4 gens of one sample share a block
    const unsigned g    = wid & 3u;
    if ((int)b >= batch) return;
    u64* t = tile[w];

    // ---- lane-parallel const precompute, stored PRE-PACKED ----
    // RY(theta) rotates by phi = theta/2. One sincosf(theta/4) gives:
    //   t = tan(theta/4), s = sin(theta/2) = 2 s4 c4
    // RY shear: nt = (-t,-t), sn = (s,s)
    // RX shear: NT = (t,-t),  SN = (-s,s)
    const float* wg = qp + g * (QDEPTH * NQ);
    {
        float a0 = wg[lane];                       // tail idx 0..31
        float s4, c4;
        __sincosf(0.25f * a0, &s4, &c4);
        float tt = __fdividef(s4, c4);
        float ss = 2.0f * s4 * c4;
        tnt2[w][lane] = pack2(-tt, -tt);
        tsn2[w][lane] = pack2(ss, ss);
        const int i1 = 32 + (int)lane;             // tail idx 32..59
        if (i1 < QDEPTH * NQ) {
            float a1 = wg[i1];
            __sincosf(0.25f * a1, &s4, &c4);
            tt = __fdividef(s4, c4);
            ss = 2.0f * s4 * c4;
            tnt2[w][i1] = pack2(-tt, -tt);
            tsn2[w][i1] = pack2(ss, ss);
        }
        if (lane < NQ) {                           // init angles
            float an = noise[(size_t)b * NQ + lane];
            __sincosf(0.25f * an, &s4, &c4);
            tt = __fdividef(s4, c4);
            ss = 2.0f * s4 * c4;
            iynt[w][lane] = pack2(-tt, -tt);
            iysn[w][lane] = pack2(ss, ss);
            irnt[w][lane] = pack2(tt, -tt);
            irsn[w][lane] = pack2(-ss, ss);
        }
    }
    __syncwarp();
    const u64* NT = tnt2[w];
    const u64* SN = tsn2[w];
    const u64* YN = iynt[w];
    const u64* YS = iysn[w];
    const u64* RN = irnt[w];
    const u64* RS = irsn[w];

    const unsigned pL   = (__popc(lane & (lane >> 1)) & 1) ? 0xFFFFFFFFu : 0u;
    const unsigned sgnA = MK_CONST ^ pL ^ ((lane & 1u)        ? 0xFFFF0000u : 0u);
    const unsigned sgnB = MK_CONST ^ pL ^ (((lane >> 4) & 1u) ? 0xAAAAAAAAu : 0u);

    // ---- state |0...0>, layout A ----
    u64 v[32];
    #pragma unroll
    for (int k = 0; k < 32; ++k) v[k] = 0ull;
    if (lane == 0) v[0] = pack2(1.0f, 0.0f);

    // ---- init: RY(n_q)+RX(n_q) on all wires ----
    init_wire<16>(v, YN, YS, RN, RS, 5);   // layout A: wires 5..9
    init_wire<8>(v,  YN, YS, RN, RS, 6);
    init_wire<4>(v,  YN, YS, RN, RS, 7);
    init_wire<2>(v,  YN, YS, RN, RS, 8);
    init_wire<1>(v,  YN, YS, RN, RS, 9);
    transpose(v, t, lane);                 // -> layout B
    init_wire<16>(v, YN, YS, RN, RS, 0);   // wires 0..4
    init_wire<8>(v,  YN, YS, RN, RS, 1);
    init_wire<4>(v,  YN, YS, RN, RS, 2);
    init_wire<2>(v,  YN, YS, RN, RS, 3);
    init_wire<1>(v,  YN, YS, RN, RS, 4);

    // ---- layers (start in layout B) ----
    #pragma unroll
    for (int l = 0; l < QDEPTH; l += 2) {
        const int w0 = l * NQ;
        half5(v, NT, SN, w0 + 0);      // layout B: wires 0..4
        transpose(v, t, lane);         // -> A
        half5(v, NT, SN, w0 + 5);      // wires 5..9
        cz_apply(v, sgnA);
        const int w1 = w0 + NQ;
        half5(v, NT, SN, w1 + 5);      // layout A: wires 5..9
        transpose(v, t, lane);         // -> B
        half5(v, NT, SN, w1 + 0);      // wires 0..4
        cz_apply(v, sgnB);
    }

    // ---- expectations ----
    float e[10];
    e[0] = exv<16>(v); e[1] = exv<8>(v); e[2] = exv<4>(v);   // layout B: wires 0..4
    e[3] = exv<2>(v);  e[4] = exv<1>(v);
    transpose(v, t, lane);                                    // -> A
    e[5] = exv<16>(v); e[6] = exv<8>(v); e[7] = exv<4>(v);   // wires 5..9
    e[8] = exv<2>(v);  e[9] = exv<1>(v);

    #pragma unroll
    for (int q = 0; q < 10; ++q) {
        float a = e[q];
        #pragma unroll
        for (int o = 16; o; o >>= 1) a += __shfl_xor_sync(0xffffffffu, a, o);
        e[q] = a;
    }
    if (lane == 0) {
        float* ob = out + (size_t)b * (NGEN * NQ) + (size_t)g * NQ;
        #pragma unroll
        for (int q = 0; q < 10; ++q) ob[q] = e[q];
    }
}

extern "C" void kernel_launch(void* const* d_in, const int* in_sizes, int n_in,
                              void* d_out, int out_size) {
    const float* noise = (const float*)d_in[0];   // (BATCH, NQ) fp32
    const float* qp    = (const float*)d_in[1];   // (NGEN, QDEPTH, NQ) fp32
    float* out = (float*)d_out;                   // (BATCH, NGEN*NQ) fp32

    int batch  = in_sizes[0] / NQ;
    int warps  = batch * NGEN;
    int blocks = (warps + WPB - 1) / WPB;
    qgen_fused<<<blocks, 32 * WPB>>>(noise, qp, out, batch);
}